// round 1
// baseline (speedup 1.0000x reference)
#include <cuda_runtime.h>
#include <cstdint>

#define Bb 2
#define Ss 2048
#define Dd 512
#define Hh 8
#define HDIM 64
#define SCALE 0.125f

// Scratch (device globals; no allocation allowed)
__device__ float g_fused[Bb*Ss*Dd];
__device__ float g_Q[Bb*Ss*Dd];
__device__ float g_K[Bb*Ss*Dd];
__device__ float g_V[Bb*Ss*Dd];
__device__ float g_att[Bb*Ss*Dd];

// ---------------------------------------------------------------------------
// Tiled SGEMM: C[M,N] = A[M,K] @ W[K,N] (+bias) (+C if accumulate)
// BM=128, BN=64, BK=16, 256 threads, each thread 8x4.
// ---------------------------------------------------------------------------
__global__ __launch_bounds__(256) void gemm_bias_kernel(
    const float* __restrict__ A, const float* __restrict__ W,
    const float* __restrict__ bias, float* __restrict__ C,
    int M, int N, int K, int accumulate)
{
    __shared__ float Ast[16][132];   // A tile transposed [k][row], padded
    __shared__ float Ws[16][64];     // W tile [k][col]

    const int tid = threadIdx.x;
    const int tx = tid & 15;         // col group
    const int ty = tid >> 4;         // row group
    const int rowBase = blockIdx.y * 128;
    const int colBase = blockIdx.x * 64;

    float acc[8][4];
    #pragma unroll
    for (int i = 0; i < 8; i++)
        #pragma unroll
        for (int j = 0; j < 4; j++) acc[i][j] = 0.f;

    for (int k0 = 0; k0 < K; k0 += 16) {
        // Load A tile: 128 rows x 16 cols (2 float4 per thread, store transposed)
        #pragma unroll
        for (int t = 0; t < 2; t++) {
            int i = tid + t * 256;          // 0..511
            int r = i >> 2;                 // 0..127
            int v = i & 3;                  // float4 index within the 16 cols
            float4 a = *(const float4*)(A + (size_t)(rowBase + r) * K + k0 + v * 4);
            Ast[v*4+0][r] = a.x;
            Ast[v*4+1][r] = a.y;
            Ast[v*4+2][r] = a.z;
            Ast[v*4+3][r] = a.w;
        }
        // Load W tile: 16 rows x 64 cols (1 float4 per thread)
        {
            int r = tid >> 4;               // 0..15
            int v = tid & 15;               // 0..15
            *(float4*)&Ws[r][v*4] =
                *(const float4*)(W + (size_t)(k0 + r) * N + colBase + v * 4);
        }
        __syncthreads();

        #pragma unroll
        for (int k = 0; k < 16; k++) {
            float4 a0 = *(float4*)&Ast[k][ty*8];
            float4 a1 = *(float4*)&Ast[k][ty*8 + 4];
            float4 b  = *(float4*)&Ws[k][tx*4];
            float ar[8] = {a0.x, a0.y, a0.z, a0.w, a1.x, a1.y, a1.z, a1.w};
            float br[4] = {b.x, b.y, b.z, b.w};
            #pragma unroll
            for (int i = 0; i < 8; i++)
                #pragma unroll
                for (int j = 0; j < 4; j++)
                    acc[i][j] += ar[i] * br[j];
        }
        __syncthreads();
    }

    // Epilogue
    float4 bv = make_float4(0.f, 0.f, 0.f, 0.f);
    if (bias) bv = *(const float4*)(bias + colBase + tx * 4);

    #pragma unroll
    for (int i = 0; i < 8; i++) {
        size_t off = (size_t)(rowBase + ty * 8 + i) * N + colBase + tx * 4;
        float4 c = make_float4(acc[i][0] + bv.x, acc[i][1] + bv.y,
                               acc[i][2] + bv.z, acc[i][3] + bv.w);
        if (accumulate) {
            float4 old = *(float4*)(C + off);
            c.x += old.x; c.y += old.y; c.z += old.z; c.w += old.w;
        }
        *(float4*)(C + off) = c;
    }
}

// ---------------------------------------------------------------------------
// Flash attention with explicit mask-zeroing of p.
// One block per (b, h, q-tile of 64). 256 threads = 16x16, each 4x4.
// Online softmax: m/l running per row; masked keys contribute exactly 0, so
// the reference's attn*M / (sum|A|+eps) reduces to acc / l (eps invisible in fp32).
// ---------------------------------------------------------------------------
__global__ __launch_bounds__(256) void flash_attn_kernel(
    const float* __restrict__ Q, const float* __restrict__ Kg,
    const float* __restrict__ Vg, const float* __restrict__ Mask,
    float* __restrict__ Out)
{
    __shared__ float Qs[64*64];   // [q][d]
    __shared__ float Vs[64*64];   // [k][d]
    __shared__ float KP[64*64];   // first K^T [d][k], then reused for P [q][k]

    const int tid = threadIdx.x;
    const int tx = tid & 15;     // output-col group (d or k tile col)
    const int ty = tid >> 4;     // row group (4 q rows)
    const int b = blockIdx.y >> 3;
    const int h = blockIdx.y & 7;
    const int q0 = blockIdx.x * 64;

    // Load Q tile
    const float* Qbase = Q + ((size_t)(b * Ss + q0)) * Dd + h * HDIM;
    #pragma unroll
    for (int t = 0; t < 4; t++) {
        int i = tid + t * 256;
        int r = i >> 4, v = i & 15;
        *(float4*)&Qs[r * 64 + v * 4] = *(const float4*)(Qbase + (size_t)r * Dd + v * 4);
    }

    float acc[4][4];
    float mrun[4], lrun[4];
    #pragma unroll
    for (int i = 0; i < 4; i++) {
        mrun[i] = -3.0e38f;
        lrun[i] = 0.f;
        #pragma unroll
        for (int j = 0; j < 4; j++) acc[i][j] = 0.f;
    }

    const float* Mbase = Mask + ((size_t)b * Ss + q0) * Ss;
    __syncthreads();

    for (int k0 = 0; k0 < Ss; k0 += 64) {
        const float* Kbase = Kg + ((size_t)(b * Ss + k0)) * Dd + h * HDIM;
        const float* Vbase = Vg + ((size_t)(b * Ss + k0)) * Dd + h * HDIM;
        // Load K (transposed into KP[d][k]) and V (natural [k][d])
        #pragma unroll
        for (int t = 0; t < 4; t++) {
            int i = tid + t * 256;
            int c = i >> 4, v = i & 15;
            float4 kv = *(const float4*)(Kbase + (size_t)c * Dd + v * 4);
            KP[(v*4+0)*64 + c] = kv.x;
            KP[(v*4+1)*64 + c] = kv.y;
            KP[(v*4+2)*64 + c] = kv.z;
            KP[(v*4+3)*64 + c] = kv.w;
            *(float4*)&Vs[c * 64 + v * 4] = *(const float4*)(Vbase + (size_t)c * Dd + v * 4);
        }
        __syncthreads();

        // S = Q @ K^T for this thread's 4x4
        float s[4][4];
        #pragma unroll
        for (int i = 0; i < 4; i++)
            #pragma unroll
            for (int j = 0; j < 4; j++) s[i][j] = 0.f;
        #pragma unroll
        for (int d = 0; d < 64; d++) {
            float a[4];
            #pragma unroll
            for (int i = 0; i < 4; i++) a[i] = Qs[(ty * 4 + i) * 64 + d];
            float4 kv = *(float4*)&KP[d * 64 + tx * 4];
            float kr[4] = {kv.x, kv.y, kv.z, kv.w};
            #pragma unroll
            for (int i = 0; i < 4; i++)
                #pragma unroll
                for (int j = 0; j < 4; j++)
                    s[i][j] += a[i] * kr[j];
        }

        // Mask (register load, coalesced float4) + online softmax update
        float mvals[4][4];
        #pragma unroll
        for (int i = 0; i < 4; i++) {
            float4 mk = *(const float4*)(Mbase + (size_t)(ty * 4 + i) * Ss + k0 + tx * 4);
            mvals[i][0] = mk.x; mvals[i][1] = mk.y; mvals[i][2] = mk.z; mvals[i][3] = mk.w;
        }

        #pragma unroll
        for (int i = 0; i < 4; i++) {
            float tm = -3.0e38f;
            #pragma unroll
            for (int j = 0; j < 4; j++) {
                s[i][j] = s[i][j] * SCALE + (mvals[i][j] == 0.f ? -1.0e9f : 0.f);
                tm = fmaxf(tm, s[i][j]);
            }
            #pragma unroll
            for (int o = 8; o >= 1; o >>= 1)
                tm = fmaxf(tm, __shfl_xor_sync(0xffffffffu, tm, o));
            float mnew = fmaxf(mrun[i], tm);
            float corr = __expf(mrun[i] - mnew);
            float ps = 0.f;
            #pragma unroll
            for (int j = 0; j < 4; j++) {
                float p = (mvals[i][j] == 0.f) ? 0.f : __expf(s[i][j] - mnew);
                s[i][j] = p;   // reuse s as p
                ps += p;
            }
            #pragma unroll
            for (int o = 8; o >= 1; o >>= 1)
                ps += __shfl_xor_sync(0xffffffffu, ps, o);
            lrun[i] = lrun[i] * corr + ps;
            mrun[i] = mnew;
            #pragma unroll
            for (int j = 0; j < 4; j++) acc[i][j] *= corr;
        }

        __syncthreads();   // done reading KP as K^T
        // Write P tile into KP [q][k]
        #pragma unroll
        for (int i = 0; i < 4; i++)
            *(float4*)&KP[(ty * 4 + i) * 64 + tx * 4] =
                make_float4(s[i][0], s[i][1], s[i][2], s[i][3]);
        __syncthreads();

        // acc += P @ V
        #pragma unroll
        for (int k = 0; k < 64; k++) {
            float pr[4];
            #pragma unroll
            for (int i = 0; i < 4; i++) pr[i] = KP[(ty * 4 + i) * 64 + k];
            float4 vv = *(float4*)&Vs[k * 64 + tx * 4];
            float vr[4] = {vv.x, vv.y, vv.z, vv.w};
            #pragma unroll
            for (int i = 0; i < 4; i++)
                #pragma unroll
                for (int j = 0; j < 4; j++)
                    acc[i][j] += pr[i] * vr[j];
        }
        __syncthreads();   // before next tile's loads overwrite KP/Vs
    }

    // Epilogue: divide by running sum (== sum|A| in reference; +eps invisible in fp32)
    #pragma unroll
    for (int i = 0; i < 4; i++) {
        float inv = (lrun[i] > 0.f) ? 1.f / lrun[i] : 0.f;
        size_t off = ((size_t)(b * Ss + q0 + ty * 4 + i)) * Dd + h * HDIM + tx * 4;
        *(float4*)(Out + off) = make_float4(acc[i][0] * inv, acc[i][1] * inv,
                                            acc[i][2] * inv, acc[i][3] * inv);
    }
}

// ---------------------------------------------------------------------------
extern "C" void kernel_launch(void* const* d_in, const int* in_sizes, int n_in,
                              void* d_out, int out_size)
{
    const float* gene = (const float*)d_in[0];
    const float* expr = (const float*)d_in[1];
    const float* Mm   = (const float*)d_in[2];
    const float* Wf   = (const float*)d_in[3];
    const float* bf   = (const float*)d_in[4];
    const float* Wq   = (const float*)d_in[5];
    const float* bq   = (const float*)d_in[6];
    const float* Wk   = (const float*)d_in[7];
    const float* bk   = (const float*)d_in[8];
    const float* Wv   = (const float*)d_in[9];
    const float* bv   = (const float*)d_in[10];
    const float* Wo   = (const float*)d_in[11];
    const float* bo   = (const float*)d_in[12];
    float* out = (float*)d_out;

    float *fused, *Qb, *Kb, *Vb, *attn;
    cudaGetSymbolAddress((void**)&fused, g_fused);
    cudaGetSymbolAddress((void**)&Qb,    g_Q);
    cudaGetSymbolAddress((void**)&Kb,    g_K);
    cudaGetSymbolAddress((void**)&Vb,    g_V);
    cudaGetSymbolAddress((void**)&attn,  g_att);

    const int Mrows = Bb * Ss;              // 4096
    dim3 block(256);
    dim3 gridP(Dd / 64, Mrows / 128);       // (8, 32)

    // fused = gene @ Wf[:512] + expr @ Wf[512:] + bf   (concat split)
    gemm_bias_kernel<<<gridP, block>>>(gene, Wf,            nullptr, fused, Mrows, Dd, Dd, 0);
    gemm_bias_kernel<<<gridP, block>>>(expr, Wf + Dd * Dd,  bf,      fused, Mrows, Dd, Dd, 1);
    // projections
    gemm_bias_kernel<<<gridP, block>>>(fused, Wq, bq, Qb, Mrows, Dd, Dd, 0);
    gemm_bias_kernel<<<gridP, block>>>(fused, Wk, bk, Kb, Mrows, Dd, Dd, 0);
    gemm_bias_kernel<<<gridP, block>>>(expr,  Wv, bv, Vb, Mrows, Dd, Dd, 0);
    // attention
    dim3 gridA(Ss / 64, Bb * Hh);           // (32, 16)
    flash_attn_kernel<<<gridA, block>>>(Qb, Kb, Vb, Mm, attn);
    // output projection
    gemm_bias_kernel<<<gridP, block>>>(attn, Wo, bo, out, Mrows, Dd, Dd, 0);
}

// round 2
// speedup vs baseline: 1.0001x; 1.0001x over previous
#include <cuda_runtime.h>
#include <cstdint>

#define Bb 2
#define Ss 2048
#define Dd 512
#define Hh 8
#define HDIM 64
#define SCALE 0.125f

// Scratch (device globals; no allocation allowed)
__device__ float g_fused[Bb*Ss*Dd];
__device__ float g_Q[Bb*Ss*Dd];
__device__ float g_K[Bb*Ss*Dd];
__device__ float g_V[Bb*Ss*Dd];
__device__ float g_att[Bb*Ss*Dd];

// ---------------------------------------------------------------------------
// Tiled SGEMM: C[M,N] = A[M,K] @ W[K,N] (+bias) (+C if accumulate)
// BM=128, BN=64, BK=16, 256 threads, each thread 8x4.
// ---------------------------------------------------------------------------
__global__ __launch_bounds__(256) void gemm_bias_kernel(
    const float* __restrict__ A, const float* __restrict__ W,
    const float* __restrict__ bias, float* __restrict__ C,
    int M, int N, int K, int accumulate)
{
    __shared__ float Ast[16][132];   // A tile transposed [k][row], padded
    __shared__ float Ws[16][64];     // W tile [k][col]

    const int tid = threadIdx.x;
    const int tx = tid & 15;         // col group
    const int ty = tid >> 4;         // row group
    const int rowBase = blockIdx.y * 128;
    const int colBase = blockIdx.x * 64;

    float acc[8][4];
    #pragma unroll
    for (int i = 0; i < 8; i++)
        #pragma unroll
        for (int j = 0; j < 4; j++) acc[i][j] = 0.f;

    for (int k0 = 0; k0 < K; k0 += 16) {
        // Load A tile: 128 rows x 16 cols (2 float4 per thread, store transposed)
        #pragma unroll
        for (int t = 0; t < 2; t++) {
            int i = tid + t * 256;          // 0..511
            int r = i >> 2;                 // 0..127
            int v = i & 3;                  // float4 index within the 16 cols
            float4 a = *(const float4*)(A + (size_t)(rowBase + r) * K + k0 + v * 4);
            Ast[v*4+0][r] = a.x;
            Ast[v*4+1][r] = a.y;
            Ast[v*4+2][r] = a.z;
            Ast[v*4+3][r] = a.w;
        }
        // Load W tile: 16 rows x 64 cols (1 float4 per thread)
        {
            int r = tid >> 4;               // 0..15
            int v = tid & 15;               // 0..15
            *(float4*)&Ws[r][v*4] =
                *(const float4*)(W + (size_t)(k0 + r) * N + colBase + v * 4);
        }
        __syncthreads();

        #pragma unroll
        for (int k = 0; k < 16; k++) {
            float4 a0 = *(float4*)&Ast[k][ty*8];
            float4 a1 = *(float4*)&Ast[k][ty*8 + 4];
            float4 b  = *(float4*)&Ws[k][tx*4];
            float ar[8] = {a0.x, a0.y, a0.z, a0.w, a1.x, a1.y, a1.z, a1.w};
            float br[4] = {b.x, b.y, b.z, b.w};
            #pragma unroll
            for (int i = 0; i < 8; i++)
                #pragma unroll
                for (int j = 0; j < 4; j++)
                    acc[i][j] += ar[i] * br[j];
        }
        __syncthreads();
    }

    // Epilogue
    float4 bv = make_float4(0.f, 0.f, 0.f, 0.f);
    if (bias) bv = *(const float4*)(bias + colBase + tx * 4);

    #pragma unroll
    for (int i = 0; i < 8; i++) {
        size_t off = (size_t)(rowBase + ty * 8 + i) * N + colBase + tx * 4;
        float4 c = make_float4(acc[i][0] + bv.x, acc[i][1] + bv.y,
                               acc[i][2] + bv.z, acc[i][3] + bv.w);
        if (accumulate) {
            float4 old = *(float4*)(C + off);
            c.x += old.x; c.y += old.y; c.z += old.z; c.w += old.w;
        }
        *(float4*)(C + off) = c;
    }
}

// ---------------------------------------------------------------------------
// Flash attention with explicit mask-zeroing of p.
// One block per (b, h, q-tile of 64). 256 threads = 16x16, each 4x4.
// Online softmax: m/l running per row; masked keys contribute exactly 0, so
// the reference's attn*M / (sum|A|+eps) reduces to acc / l (eps invisible in fp32).
// ---------------------------------------------------------------------------
__global__ __launch_bounds__(256) void flash_attn_kernel(
    const float* __restrict__ Q, const float* __restrict__ Kg,
    const float* __restrict__ Vg, const float* __restrict__ Mask,
    float* __restrict__ Out)
{
    __shared__ float Qs[64*64];   // [q][d]
    __shared__ float Vs[64*64];   // [k][d]
    __shared__ float KP[64*64];   // first K^T [d][k], then reused for P [q][k]

    const int tid = threadIdx.x;
    const int tx = tid & 15;     // output-col group (d or k tile col)
    const int ty = tid >> 4;     // row group (4 q rows)
    const int b = blockIdx.y >> 3;
    const int h = blockIdx.y & 7;
    const int q0 = blockIdx.x * 64;

    // Load Q tile
    const float* Qbase = Q + ((size_t)(b * Ss + q0)) * Dd + h * HDIM;
    #pragma unroll
    for (int t = 0; t < 4; t++) {
        int i = tid + t * 256;
        int r = i >> 4, v = i & 15;
        *(float4*)&Qs[r * 64 + v * 4] = *(const float4*)(Qbase + (size_t)r * Dd + v * 4);
    }

    float acc[4][4];
    float mrun[4], lrun[4];
    #pragma unroll
    for (int i = 0; i < 4; i++) {
        mrun[i] = -3.0e38f;
        lrun[i] = 0.f;
        #pragma unroll
        for (int j = 0; j < 4; j++) acc[i][j] = 0.f;
    }

    const float* Mbase = Mask + ((size_t)b * Ss + q0) * Ss;
    __syncthreads();

    for (int k0 = 0; k0 < Ss; k0 += 64) {
        const float* Kbase = Kg + ((size_t)(b * Ss + k0)) * Dd + h * HDIM;
        const float* Vbase = Vg + ((size_t)(b * Ss + k0)) * Dd + h * HDIM;
        // Load K (transposed into KP[d][k]) and V (natural [k][d])
        #pragma unroll
        for (int t = 0; t < 4; t++) {
            int i = tid + t * 256;
            int c = i >> 4, v = i & 15;
            float4 kv = *(const float4*)(Kbase + (size_t)c * Dd + v * 4);
            KP[(v*4+0)*64 + c] = kv.x;
            KP[(v*4+1)*64 + c] = kv.y;
            KP[(v*4+2)*64 + c] = kv.z;
            KP[(v*4+3)*64 + c] = kv.w;
            *(float4*)&Vs[c * 64 + v * 4] = *(const float4*)(Vbase + (size_t)c * Dd + v * 4);
        }
        __syncthreads();

        // S = Q @ K^T for this thread's 4x4
        float s[4][4];
        #pragma unroll
        for (int i = 0; i < 4; i++)
            #pragma unroll
            for (int j = 0; j < 4; j++) s[i][j] = 0.f;
        #pragma unroll
        for (int d = 0; d < 64; d++) {
            float a[4];
            #pragma unroll
            for (int i = 0; i < 4; i++) a[i] = Qs[(ty * 4 + i) * 64 + d];
            float4 kv = *(float4*)&KP[d * 64 + tx * 4];
            float kr[4] = {kv.x, kv.y, kv.z, kv.w};
            #pragma unroll
            for (int i = 0; i < 4; i++)
                #pragma unroll
                for (int j = 0; j < 4; j++)
                    s[i][j] += a[i] * kr[j];
        }

        // Mask (register load, coalesced float4) + online softmax update
        float mvals[4][4];
        #pragma unroll
        for (int i = 0; i < 4; i++) {
            float4 mk = *(const float4*)(Mbase + (size_t)(ty * 4 + i) * Ss + k0 + tx * 4);
            mvals[i][0] = mk.x; mvals[i][1] = mk.y; mvals[i][2] = mk.z; mvals[i][3] = mk.w;
        }

        #pragma unroll
        for (int i = 0; i < 4; i++) {
            float tm = -3.0e38f;
            #pragma unroll
            for (int j = 0; j < 4; j++) {
                s[i][j] = s[i][j] * SCALE + (mvals[i][j] == 0.f ? -1.0e9f : 0.f);
                tm = fmaxf(tm, s[i][j]);
            }
            #pragma unroll
            for (int o = 8; o >= 1; o >>= 1)
                tm = fmaxf(tm, __shfl_xor_sync(0xffffffffu, tm, o));
            float mnew = fmaxf(mrun[i], tm);
            float corr = __expf(mrun[i] - mnew);
            float ps = 0.f;
            #pragma unroll
            for (int j = 0; j < 4; j++) {
                float p = (mvals[i][j] == 0.f) ? 0.f : __expf(s[i][j] - mnew);
                s[i][j] = p;   // reuse s as p
                ps += p;
            }
            #pragma unroll
            for (int o = 8; o >= 1; o >>= 1)
                ps += __shfl_xor_sync(0xffffffffu, ps, o);
            lrun[i] = lrun[i] * corr + ps;
            mrun[i] = mnew;
            #pragma unroll
            for (int j = 0; j < 4; j++) acc[i][j] *= corr;
        }

        __syncthreads();   // done reading KP as K^T
        // Write P tile into KP [q][k]
        #pragma unroll
        for (int i = 0; i < 4; i++)
            *(float4*)&KP[(ty * 4 + i) * 64 + tx * 4] =
                make_float4(s[i][0], s[i][1], s[i][2], s[i][3]);
        __syncthreads();

        // acc += P @ V
        #pragma unroll
        for (int k = 0; k < 64; k++) {
            float pr[4];
            #pragma unroll
            for (int i = 0; i < 4; i++) pr[i] = KP[(ty * 4 + i) * 64 + k];
            float4 vv = *(float4*)&Vs[k * 64 + tx * 4];
            float vr[4] = {vv.x, vv.y, vv.z, vv.w};
            #pragma unroll
            for (int i = 0; i < 4; i++)
                #pragma unroll
                for (int j = 0; j < 4; j++)
                    acc[i][j] += pr[i] * vr[j];
        }
        __syncthreads();   // before next tile's loads overwrite KP/Vs
    }

    // Epilogue: divide by running sum (== sum|A| in reference; +eps invisible in fp32)
    #pragma unroll
    for (int i = 0; i < 4; i++) {
        float inv = (lrun[i] > 0.f) ? 1.f / lrun[i] : 0.f;
        size_t off = ((size_t)(b * Ss + q0 + ty * 4 + i)) * Dd + h * HDIM + tx * 4;
        *(float4*)(Out + off) = make_float4(acc[i][0] * inv, acc[i][1] * inv,
                                            acc[i][2] * inv, acc[i][3] * inv);
    }
}

// ---------------------------------------------------------------------------
extern "C" void kernel_launch(void* const* d_in, const int* in_sizes, int n_in,
                              void* d_out, int out_size)
{
    const float* gene = (const float*)d_in[0];
    const float* expr = (const float*)d_in[1];
    const float* Mm   = (const float*)d_in[2];
    const float* Wf   = (const float*)d_in[3];
    const float* bf   = (const float*)d_in[4];
    const float* Wq   = (const float*)d_in[5];
    const float* bq   = (const float*)d_in[6];
    const float* Wk   = (const float*)d_in[7];
    const float* bk   = (const float*)d_in[8];
    const float* Wv   = (const float*)d_in[9];
    const float* bv   = (const float*)d_in[10];
    const float* Wo   = (const float*)d_in[11];
    const float* bo   = (const float*)d_in[12];
    float* out = (float*)d_out;

    float *fused, *Qb, *Kb, *Vb, *attn;
    cudaGetSymbolAddress((void**)&fused, g_fused);
    cudaGetSymbolAddress((void**)&Qb,    g_Q);
    cudaGetSymbolAddress((void**)&Kb,    g_K);
    cudaGetSymbolAddress((void**)&Vb,    g_V);
    cudaGetSymbolAddress((void**)&attn,  g_att);

    const int Mrows = Bb * Ss;              // 4096
    dim3 block(256);
    dim3 gridP(Dd / 64, Mrows / 128);       // (8, 32)

    // fused = gene @ Wf[:512] + expr @ Wf[512:] + bf   (concat split)
    gemm_bias_kernel<<<gridP, block>>>(gene, Wf,            nullptr, fused, Mrows, Dd, Dd, 0);
    gemm_bias_kernel<<<gridP, block>>>(expr, Wf + Dd * Dd,  bf,      fused, Mrows, Dd, Dd, 1);
    // projections
    gemm_bias_kernel<<<gridP, block>>>(fused, Wq, bq, Qb, Mrows, Dd, Dd, 0);
    gemm_bias_kernel<<<gridP, block>>>(fused, Wk, bk, Kb, Mrows, Dd, Dd, 0);
    gemm_bias_kernel<<<gridP, block>>>(expr,  Wv, bv, Vb, Mrows, Dd, Dd, 0);
    // attention
    dim3 gridA(Ss / 64, Bb * Hh);           // (32, 16)
    flash_attn_kernel<<<gridA, block>>>(Qb, Kb, Vb, Mm, attn);
    // output projection
    gemm_bias_kernel<<<gridP, block>>>(attn, Wo, bo, out, Mrows, Dd, Dd, 0);
}

// round 4
// speedup vs baseline: 2.5421x; 2.5419x over previous
#include <cuda_runtime.h>
#include <cuda_bf16.h>
#include <cstdint>

#define Bb 2
#define Ss 2048
#define Dd 512
#define Hh 8
#define HDIM 64
#define SCALE 0.125f

__device__ float g_fused[Bb*Ss*Dd];
__device__ float g_Q[Bb*Ss*Dd];
__device__ float g_K[Bb*Ss*Dd];
__device__ float g_V[Bb*Ss*Dd];
__device__ float g_att[Bb*Ss*Dd];
__device__ uint32_t g_mbits[Bb*Ss*(Ss/32)];

// ---------------------------------------------------------------------------
__device__ __forceinline__ uint32_t smem_u32(const void* p) {
    return (uint32_t)__cvta_generic_to_shared(p);
}
__device__ __forceinline__ void split2(float x, float y, uint32_t &hi, uint32_t &lo) {
    __nv_bfloat162 h = __floats2bfloat162_rn(x, y);
    float2 hf = __bfloat1622float2(h);
    __nv_bfloat162 l = __floats2bfloat162_rn(x - hf.x, y - hf.y);
    hi = reinterpret_cast<uint32_t&>(h);
    lo = reinterpret_cast<uint32_t&>(l);
}
__device__ __forceinline__ void mma16816(float c[4], const uint32_t* a, const uint32_t* b) {
    asm volatile(
        "mma.sync.aligned.m16n8k16.row.col.f32.bf16.bf16.f32 "
        "{%0,%1,%2,%3}, {%4,%5,%6,%7}, {%8,%9}, {%0,%1,%2,%3};\n"
        : "+f"(c[0]), "+f"(c[1]), "+f"(c[2]), "+f"(c[3])
        : "r"(a[0]), "r"(a[1]), "r"(a[2]), "r"(a[3]), "r"(b[0]), "r"(b[1]));
}
__device__ __forceinline__ void ldsm_x4(uint32_t a[4], uint32_t addr) {
    asm volatile("ldmatrix.sync.aligned.m8n8.x4.shared.b16 {%0,%1,%2,%3}, [%4];"
        : "=r"(a[0]), "=r"(a[1]), "=r"(a[2]), "=r"(a[3]) : "r"(addr));
}
__device__ __forceinline__ void ldsm_x4_t(uint32_t a[4], uint32_t addr) {
    asm volatile("ldmatrix.sync.aligned.m8n8.x4.trans.shared.b16 {%0,%1,%2,%3}, [%4];"
        : "=r"(a[0]), "=r"(a[1]), "=r"(a[2]), "=r"(a[3]) : "r"(addr));
}

// ---------------------------------------------------------------------------
// Mask bit-pack: bit k of word = (M[...][k] != 0)
// ---------------------------------------------------------------------------
__global__ __launch_bounds__(256) void maskbits_kernel(const float* __restrict__ M,
                                                       uint32_t* __restrict__ bits) {
    int idx = blockIdx.x * 256 + threadIdx.x;
    float v = M[idx];
    uint32_t b = __ballot_sync(0xffffffffu, v != 0.f);
    if ((threadIdx.x & 31) == 0) bits[idx >> 5] = b;
}

// ---------------------------------------------------------------------------
// bf16x3 tensor-core GEMM: C[4096][512] = A[4096][K] @ W[K][512] + bias
// A row stride fixed 512; for K=1024 rows come from A1 (k<512) then A2.
// BM=128 BN=64 BK=32; 8 warps (4m x 2n), warp tile 32x32.
// ---------------------------------------------------------------------------
#define GA_STR 40
#define GB_STR 72

__global__ __launch_bounds__(256) void gemm3_kernel(
    const float* __restrict__ A1, const float* __restrict__ A2,
    const float* __restrict__ W, const float* __restrict__ bias,
    float* __restrict__ C, int K)
{
    __shared__ uint16_t Ah[128*GA_STR], Al[128*GA_STR];
    __shared__ uint16_t Bh[32*GB_STR],  Bl[32*GB_STR];

    const int tid  = threadIdx.x;
    const int lane = tid & 31, wid = tid >> 5;
    const int grp  = lane >> 2, tig = lane & 3;
    const int wm = (wid & 3) * 32, wn = (wid >> 2) * 32;
    const int rowBase = blockIdx.y * 128, colBase = blockIdx.x * 64;

    const int arow = ((lane >> 3) & 1) * 8 + (lane & 7);
    const int acol = (lane >> 4) * 8;
    const int brow = ((lane >> 3) & 1) * 8 + (lane & 7);   // trans pattern
    const int bcol = (lane >> 4) * 8;

    float acc[2][4][4];
    #pragma unroll
    for (int mt = 0; mt < 2; mt++)
        #pragma unroll
        for (int nt = 0; nt < 4; nt++)
            #pragma unroll
            for (int j = 0; j < 4; j++) acc[mt][nt][j] = 0.f;

    for (int k0 = 0; k0 < K; k0 += 32) {
        const float* Ap = (k0 < Dd) ? A1 : A2;
        const int ka = k0 & (Dd - 1);
        #pragma unroll
        for (int i = 0; i < 4; i++) {
            int idx = tid + i * 256;
            int r = idx >> 3, v = idx & 7;
            float4 a = *(const float4*)(Ap + (size_t)(rowBase + r) * Dd + ka + v * 4);
            uint32_t h0, l0, h1, l1;
            split2(a.x, a.y, h0, l0);
            split2(a.z, a.w, h1, l1);
            *(uint2*)&Ah[r * GA_STR + v * 4] = make_uint2(h0, h1);
            *(uint2*)&Al[r * GA_STR + v * 4] = make_uint2(l0, l1);
        }
        #pragma unroll
        for (int i = 0; i < 2; i++) {
            int idx = tid + i * 256;
            int r = idx >> 4, v = idx & 15;
            float4 w4 = *(const float4*)(W + (size_t)(k0 + r) * Dd + colBase + v * 4);
            uint32_t h0, l0, h1, l1;
            split2(w4.x, w4.y, h0, l0);
            split2(w4.z, w4.w, h1, l1);
            *(uint2*)&Bh[r * GB_STR + v * 4] = make_uint2(h0, h1);
            *(uint2*)&Bl[r * GB_STR + v * 4] = make_uint2(l0, l1);
        }
        __syncthreads();

        #pragma unroll
        for (int kk = 0; kk < 2; kk++) {
            uint32_t ah[2][4], al[2][4];
            #pragma unroll
            for (int mt = 0; mt < 2; mt++) {
                int off = (wm + mt * 16 + arow) * GA_STR + kk * 16 + acol;
                ldsm_x4(ah[mt], smem_u32(&Ah[off]));
                ldsm_x4(al[mt], smem_u32(&Al[off]));
            }
            #pragma unroll
            for (int nt2 = 0; nt2 < 2; nt2++) {
                uint32_t th[4], tl[4];
                int off = (kk * 16 + brow) * GB_STR + wn + nt2 * 16 + bcol;
                ldsm_x4_t(th, smem_u32(&Bh[off]));
                ldsm_x4_t(tl, smem_u32(&Bl[off]));
                #pragma unroll
                for (int mt = 0; mt < 2; mt++) {
                    mma16816(acc[mt][nt2*2],   ah[mt], th);
                    mma16816(acc[mt][nt2*2],   al[mt], th);
                    mma16816(acc[mt][nt2*2],   ah[mt], tl);
                    mma16816(acc[mt][nt2*2+1], ah[mt], th + 2);
                    mma16816(acc[mt][nt2*2+1], al[mt], th + 2);
                    mma16816(acc[mt][nt2*2+1], ah[mt], tl + 2);
                }
            }
        }
        __syncthreads();
    }

    #pragma unroll
    for (int mt = 0; mt < 2; mt++)
        #pragma unroll
        for (int nt = 0; nt < 4; nt++) {
            int row = rowBase + wm + mt * 16 + grp;
            int col = colBase + wn + nt * 8 + 2 * tig;
            float bx = bias[col], by = bias[col + 1];
            *(float2*)(C + (size_t)row * Dd + col) =
                make_float2(acc[mt][nt][0] + bx, acc[mt][nt][1] + by);
            *(float2*)(C + (size_t)(row + 8) * Dd + col) =
                make_float2(acc[mt][nt][2] + bx, acc[mt][nt][3] + by);
        }
}

// ---------------------------------------------------------------------------
// Tensor-core flash attention. 4 warps; warp w owns q rows w*16..+15.
// BK=64 per tile. bf16x3 for QK^T and PV. Mask via bitfield; masked p = 0,
// so running l == reference's sum|A| and final divide matches the reference.
// ---------------------------------------------------------------------------
#define FSTR 72

__global__ __launch_bounds__(128) void flash_mma_kernel(
    const float* __restrict__ Q, const float* __restrict__ Kg,
    const float* __restrict__ Vg, const uint32_t* __restrict__ mbits,
    float* __restrict__ Out)
{
    __shared__ uint16_t Kh[64*FSTR], Kl[64*FSTR], Vh[64*FSTR], Vl[64*FSTR];
    const int tid = threadIdx.x, lane = tid & 31, w = tid >> 5;
    const int grp = lane >> 2, tig = lane & 3;
    const int b = blockIdx.y >> 3, h = blockIdx.y & 7;
    const int q0 = blockIdx.x * 64;

    const int arow = ((lane >> 3) & 1) * 8 + (lane & 7);   // A / trans-B pattern
    const int acol = (lane >> 4) * 8;
    const int brow = (lane >> 4) * 8 + (lane & 7);          // non-trans B (K) pattern
    const int bcol = ((lane >> 3) & 1) * 8;

    // ---- stage Q (pre-scaled) through Kh/Kl, pull A-frags into registers ----
    const float* Qb = Q + ((size_t)(b * Ss + q0)) * Dd + h * HDIM;
    #pragma unroll
    for (int i = 0; i < 8; i++) {
        int r = (tid >> 4) + i * 8, v = tid & 15;
        float4 qv = *(const float4*)(Qb + (size_t)r * Dd + v * 4);
        uint32_t h0, l0, h1, l1;
        split2(qv.x * SCALE, qv.y * SCALE, h0, l0);
        split2(qv.z * SCALE, qv.w * SCALE, h1, l1);
        *(uint2*)&Kh[r * FSTR + v * 4] = make_uint2(h0, h1);
        *(uint2*)&Kl[r * FSTR + v * 4] = make_uint2(l0, l1);
    }
    __syncthreads();
    uint32_t qh[4][4], ql[4][4];
    #pragma unroll
    for (int c = 0; c < 4; c++) {
        int off = (w * 16 + arow) * FSTR + c * 16 + acol;
        ldsm_x4(qh[c], smem_u32(&Kh[off]));
        ldsm_x4(ql[c], smem_u32(&Kl[off]));
    }
    __syncthreads();

    float oacc[8][4];
    #pragma unroll
    for (int n = 0; n < 8; n++)
        #pragma unroll
        for (int j = 0; j < 4; j++) oacc[n][j] = 0.f;
    float mrun[2] = {-3.0e38f, -3.0e38f}, lrun[2] = {0.f, 0.f};

    for (int k0 = 0; k0 < Ss; k0 += 64) {
        const float* Kb = Kg + ((size_t)(b * Ss + k0)) * Dd + h * HDIM;
        const float* Vb = Vg + ((size_t)(b * Ss + k0)) * Dd + h * HDIM;
        #pragma unroll
        for (int i = 0; i < 8; i++) {
            int r = (tid >> 4) + i * 8, v = tid & 15;
            uint32_t h0, l0, h1, l1;
            float4 kv = *(const float4*)(Kb + (size_t)r * Dd + v * 4);
            split2(kv.x, kv.y, h0, l0); split2(kv.z, kv.w, h1, l1);
            *(uint2*)&Kh[r * FSTR + v * 4] = make_uint2(h0, h1);
            *(uint2*)&Kl[r * FSTR + v * 4] = make_uint2(l0, l1);
            float4 vv = *(const float4*)(Vb + (size_t)r * Dd + v * 4);
            split2(vv.x, vv.y, h0, l0); split2(vv.z, vv.w, h1, l1);
            *(uint2*)&Vh[r * FSTR + v * 4] = make_uint2(h0, h1);
            *(uint2*)&Vl[r * FSTR + v * 4] = make_uint2(l0, l1);
        }
        __syncthreads();

        // S = Qs @ K^T
        float sacc[8][4];
        #pragma unroll
        for (int n = 0; n < 8; n++)
            #pragma unroll
            for (int j = 0; j < 4; j++) sacc[n][j] = 0.f;
        #pragma unroll
        for (int g = 0; g < 4; g++)
            #pragma unroll
            for (int c = 0; c < 4; c++) {
                uint32_t kf[4], kfl[4];
                int off = (g * 16 + brow) * FSTR + c * 16 + bcol;
                ldsm_x4(kf,  smem_u32(&Kh[off]));
                ldsm_x4(kfl, smem_u32(&Kl[off]));
                mma16816(sacc[2*g],   qh[c], kf);
                mma16816(sacc[2*g],   ql[c], kf);
                mma16816(sacc[2*g],   qh[c], kfl);
                mma16816(sacc[2*g+1], qh[c], kf + 2);
                mma16816(sacc[2*g+1], ql[c], kf + 2);
                mma16816(sacc[2*g+1], qh[c], kfl + 2);
            }

        // ---- masked online softmax (register-resident) ----
        #pragma unroll
        for (int r = 0; r < 2; r++) {
            int qrow = q0 + w * 16 + grp + r * 8;
            size_t mb = ((size_t)(b * Ss) + qrow) * (Ss / 32) + (k0 >> 5);
            uint32_t bw0 = mbits[mb], bw1 = mbits[mb + 1];
            float tm = -3.0e38f;
            #pragma unroll
            for (int n = 0; n < 8; n++)
                #pragma unroll
                for (int e = 0; e < 2; e++) {
                    int col = n * 8 + 2 * tig + e;
                    uint32_t on = ((n < 4 ? bw0 : bw1) >> (col & 31)) & 1u;
                    float sv = on ? sacc[n][r*2+e] : -1.0e9f;
                    sacc[n][r*2+e] = sv;
                    tm = fmaxf(tm, sv);
                }
            tm = fmaxf(tm, __shfl_xor_sync(0xffffffffu, tm, 1));
            tm = fmaxf(tm, __shfl_xor_sync(0xffffffffu, tm, 2));
            float mn = fmaxf(mrun[r], tm);
            float co = __expf(mrun[r] - mn);
            float ps = 0.f;
            #pragma unroll
            for (int n = 0; n < 8; n++)
                #pragma unroll
                for (int e = 0; e < 2; e++) {
                    float sv = sacc[n][r*2+e];
                    float p = (sv == -1.0e9f) ? 0.f : __expf(sv - mn);
                    sacc[n][r*2+e] = p;
                    ps += p;
                }
            ps += __shfl_xor_sync(0xffffffffu, ps, 1);
            ps += __shfl_xor_sync(0xffffffffu, ps, 2);
            mrun[r] = mn;
            lrun[r] = lrun[r] * co + ps;
            #pragma unroll
            for (int n = 0; n < 8; n++) {
                oacc[n][r*2]   *= co;
                oacc[n][r*2+1] *= co;
            }
        }

        // ---- O += P @ V  (P c-frags -> A-frags in registers) ----
        #pragma unroll
        for (int kc = 0; kc < 4; kc++) {
            uint32_t ah[4], al[4];
            split2(sacc[2*kc][0],   sacc[2*kc][1],   ah[0], al[0]);
            split2(sacc[2*kc][2],   sacc[2*kc][3],   ah[1], al[1]);
            split2(sacc[2*kc+1][0], sacc[2*kc+1][1], ah[2], al[2]);
            split2(sacc[2*kc+1][2], sacc[2*kc+1][3], ah[3], al[3]);
            #pragma unroll
            for (int c = 0; c < 4; c++) {
                uint32_t vf[4], vfl[4];
                int off = (kc * 16 + arow) * FSTR + c * 16 + acol;
                ldsm_x4_t(vf,  smem_u32(&Vh[off]));
                ldsm_x4_t(vfl, smem_u32(&Vl[off]));
                mma16816(oacc[2*c],   ah, vf);
                mma16816(oacc[2*c],   al, vf);
                mma16816(oacc[2*c],   ah, vfl);
                mma16816(oacc[2*c+1], ah, vf + 2);
                mma16816(oacc[2*c+1], al, vf + 2);
                mma16816(oacc[2*c+1], ah, vfl + 2);
            }
        }
        __syncthreads();
    }

    // ---- epilogue ----
    float inv0 = (lrun[0] > 0.f) ? 1.f / lrun[0] : 0.f;
    float inv1 = (lrun[1] > 0.f) ? 1.f / lrun[1] : 0.f;
    int row0 = b * Ss + q0 + w * 16 + grp;
    #pragma unroll
    for (int n = 0; n < 8; n++) {
        int col = h * HDIM + n * 8 + 2 * tig;
        *(float2*)(Out + (size_t)row0 * Dd + col) =
            make_float2(oacc[n][0] * inv0, oacc[n][1] * inv0);
        *(float2*)(Out + (size_t)(row0 + 8) * Dd + col) =
            make_float2(oacc[n][2] * inv1, oacc[n][3] * inv1);
    }
}

// ---------------------------------------------------------------------------
extern "C" void kernel_launch(void* const* d_in, const int* in_sizes, int n_in,
                              void* d_out, int out_size)
{
    const float* gene = (const float*)d_in[0];
    const float* expr = (const float*)d_in[1];
    const float* Mm   = (const float*)d_in[2];
    const float* Wf   = (const float*)d_in[3];
    const float* bf   = (const float*)d_in[4];
    const float* Wq   = (const float*)d_in[5];
    const float* bq   = (const float*)d_in[6];
    const float* Wk   = (const float*)d_in[7];
    const float* bk   = (const float*)d_in[8];
    const float* Wv   = (const float*)d_in[9];
    const float* bv   = (const float*)d_in[10];
    const float* Wo   = (const float*)d_in[11];
    const float* bo   = (const float*)d_in[12];
    float* out = (float*)d_out;

    float *fused, *Qb, *Kb, *Vb, *attn;
    uint32_t* mbits;
    cudaGetSymbolAddress((void**)&fused, g_fused);
    cudaGetSymbolAddress((void**)&Qb,    g_Q);
    cudaGetSymbolAddress((void**)&Kb,    g_K);
    cudaGetSymbolAddress((void**)&Vb,    g_V);
    cudaGetSymbolAddress((void**)&attn,  g_att);
    cudaGetSymbolAddress((void**)&mbits, g_mbits);

    const int Mrows = Bb * Ss;                   // 4096
    dim3 gridP(Dd / 64, Mrows / 128);            // (8, 32)

    maskbits_kernel<<<(Bb * Ss * Ss) / 256, 256>>>(Mm, mbits);
    // fused = [gene; expr] @ Wf + bf  (single K=1024 pass, A switches at k=512)
    gemm3_kernel<<<gridP, 256>>>(gene, expr, Wf, bf, fused, 2 * Dd);
    gemm3_kernel<<<gridP, 256>>>(fused, fused, Wq, bq, Qb, Dd);
    gemm3_kernel<<<gridP, 256>>>(fused, fused, Wk, bk, Kb, Dd);
    gemm3_kernel<<<gridP, 256>>>(expr,  expr,  Wv, bv, Vb, Dd);

    dim3 gridA(Ss / 64, Bb * Hh);                // (32, 16)
    flash_mma_kernel<<<gridA, 128>>>(Qb, Kb, Vb, mbits, attn);

    gemm3_kernel<<<gridP, 256>>>(attn, attn, Wo, bo, out, Dd);
}